// round 2
// baseline (speedup 1.0000x reference)
#include <cuda_runtime.h>
#include <cuda_bf16.h>
#include <math.h>

// ---------------------------------------------------------------------------
// FraudGNN: 3-layer GCN on N=50000 nodes, E=800000 edges.
//   L1: GCNConv(128->128) -> BN -> ReLU
//   L2: GCNConv(128->64)  -> BN -> ReLU
//   L3: GCNConv(64->2)    -> log_softmax
// GCNConv: out = D^{-1/2}(A+I)D^{-1/2} (X W) + b  with in-degree incl self-loop.
// NOTE: edge_index is int32 on device (JAX x64 disabled downcasts int64).
// ---------------------------------------------------------------------------

#define NMAX 50000

// Scratch (static device globals; no allocation in kernel_launch)
__device__ float g_bufA[NMAX * 128];
__device__ float g_bufB[NMAX * 128];
__device__ float g_dinv[NMAX];
__device__ float g_deg[NMAX];
__device__ float g_stats[256];   // [0..127] sum, [128..255] sumsq

// ---------------------------------------------------------------------------
__global__ void zero_kernel(float* __restrict__ p, long long n) {
    long long i = blockIdx.x * (long long)blockDim.x + threadIdx.x;
    if (i < n) p[i] = 0.0f;
}

__global__ void deg_kernel(const int* __restrict__ ei, long long E,
                           float* __restrict__ deg) {
    long long e = blockIdx.x * (long long)blockDim.x + threadIdx.x;
    if (e < E) {
        int d = ei[E + e];      // dst row
        atomicAdd(&deg[d], 1.0f);
    }
}

__global__ void dinv_kernel(const float* __restrict__ deg,
                            float* __restrict__ dinv, int n) {
    int i = blockIdx.x * blockDim.x + threadIdx.x;
    if (i < n) dinv[i] = rsqrtf(deg[i] + 1.0f);   // +1 self-loop
}

// ---------------------------------------------------------------------------
// GEMM: out[n,M] = X[n,K] @ W[K,M]. W held in shared (row-major, conflict-free
// scalar reads: same k across threads, consecutive cols -> consecutive banks).
template <int K, int M>
__global__ void gemm_kernel(const float* __restrict__ X,
                            const float* __restrict__ W,
                            float* __restrict__ out, int n) {
    extern __shared__ float sh[];
    float* Ws = sh;              // K*M
    float* xs = sh + K * M;      // RPI*K
    constexpr int RPI = 256 / M; // rows per iteration

    for (int i = threadIdx.x; i < K * M; i += 256) Ws[i] = W[i];

    const int col = threadIdx.x % M;
    const int r   = threadIdx.x / M;

    int base = blockIdx.x * RPI;
    // cooperative load of RPI rows of X
    __syncthreads();
    for (int i = threadIdx.x; i < RPI * K; i += 256) {
        int rr = i / K, kk = i % K;
        int row = base + rr;
        xs[i] = (row < n) ? X[(long long)row * K + kk] : 0.0f;
    }
    __syncthreads();

    int row = base + r;
    if (row < n) {
        float acc = 0.0f;
        const float* xrow = xs + r * K;
#pragma unroll
        for (int k = 0; k < K; k++) acc = fmaf(xrow[k], Ws[k * M + col], acc);
        out[(long long)row * M + col] = acc;
    }
}

// ---------------------------------------------------------------------------
// Edge aggregation: out[dst] += h[src] * dinv[src]*dinv[dst]. One float4 of
// features per thread; F/4 threads per edge.
template <int F>
__global__ void aggregate_kernel(const int* __restrict__ ei, long long E,
                                 const float* __restrict__ h,
                                 const float* __restrict__ dinv,
                                 float* __restrict__ out) {
    constexpr int C4 = F / 4;
    long long tid = blockIdx.x * (long long)blockDim.x + threadIdx.x;
    long long e = tid / C4;
    int c = (int)(tid % C4);
    if (e >= E) return;
    int s = ei[e];
    int d = ei[E + e];
    float norm = dinv[s] * dinv[d];
    const float4* hs = (const float4*)(h + (long long)s * F);
    float4 v = hs[c];
    float* o = out + (long long)d * F + c * 4;
    atomicAdd(o + 0, v.x * norm);
    atomicAdd(o + 1, v.y * norm);
    atomicAdd(o + 2, v.z * norm);
    atomicAdd(o + 3, v.w * norm);
}

// F == 2 version: one thread per edge.
__global__ void aggregate2_kernel(const int* __restrict__ ei, long long E,
                                  const float* __restrict__ h,
                                  const float* __restrict__ dinv,
                                  float* __restrict__ out) {
    long long e = blockIdx.x * (long long)blockDim.x + threadIdx.x;
    if (e >= E) return;
    int s = ei[e];
    int d = ei[E + e];
    float norm = dinv[s] * dinv[d];
    float2 v = *(const float2*)(h + (long long)s * 2);
    atomicAdd(out + (long long)d * 2 + 0, v.x * norm);
    atomicAdd(out + (long long)d * 2 + 1, v.y * norm);
}

// Self-loop term + bias: out[v,f] += h[v,f]*dinv[v]^2 + b[f]  (runs after edge
// aggregation kernel; stream-serialized so plain add is safe).
template <int F>
__global__ void selfloop_bias_kernel(const float* __restrict__ h,
                                     const float* __restrict__ dinv,
                                     const float* __restrict__ b,
                                     float* __restrict__ out, int n) {
    long long total = (long long)n * F;
    long long i = blockIdx.x * (long long)blockDim.x + threadIdx.x;
    if (i >= total) return;
    int node = (int)(i / F);
    int f = (int)(i % F);
    float dv = dinv[node];
    out[i] += h[i] * dv * dv + b[f];
}

// ---------------------------------------------------------------------------
// BN stats: per-feature sum and sumsq over n rows.
template <int M>
__global__ void bn_stats_kernel(const float* __restrict__ x, int n,
                                float* __restrict__ stats) {
    __shared__ float ssum[M];
    __shared__ float ssq[M];
    for (int i = threadIdx.x; i < M; i += blockDim.x) { ssum[i] = 0.f; ssq[i] = 0.f; }
    __syncthreads();
    long long total = (long long)n * M;
    for (long long i = blockIdx.x * (long long)blockDim.x + threadIdx.x;
         i < total; i += (long long)gridDim.x * blockDim.x) {
        float v = x[i];
        int f = (int)(i % M);
        atomicAdd(&ssum[f], v);
        atomicAdd(&ssq[f], v * v);
    }
    __syncthreads();
    for (int i = threadIdx.x; i < M; i += blockDim.x) {
        atomicAdd(&stats[i], ssum[i]);
        atomicAdd(&stats[128 + i], ssq[i]);
    }
}

template <int M>
__global__ void bn_apply_relu_kernel(float* __restrict__ x, int n,
                                     const float* __restrict__ stats,
                                     const float* __restrict__ g,
                                     const float* __restrict__ beta) {
    long long total = (long long)n * M;
    long long i = blockIdx.x * (long long)blockDim.x + threadIdx.x;
    if (i >= total) return;
    int f = (int)(i % M);
    float inv_n = 1.0f / (float)n;
    float m = stats[f] * inv_n;
    float v = stats[128 + f] * inv_n - m * m;
    float y = (x[i] - m) * rsqrtf(v + 1e-5f) * g[f] + beta[f];
    x[i] = fmaxf(y, 0.0f);
}

__global__ void logsoftmax2_kernel(const float* __restrict__ h,
                                   float* __restrict__ out, int n) {
    int i = blockIdx.x * blockDim.x + threadIdx.x;
    if (i >= n) return;
    float a = h[2 * i], b = h[2 * i + 1];
    float m = fmaxf(a, b);
    float l = m + logf(expf(a - m) + expf(b - m));
    out[2 * i] = a - l;
    out[2 * i + 1] = b - l;
}

// ---------------------------------------------------------------------------
template <int K, int M>
static void launch_gemm(const float* X, const float* W, float* out, int n) {
    constexpr int RPI = 256 / M;
    size_t sh = (size_t)(K * M + RPI * K) * sizeof(float);
    static bool attr_set = false;
    if (!attr_set) {
        cudaFuncSetAttribute(gemm_kernel<K, M>,
                             cudaFuncAttributeMaxDynamicSharedMemorySize, 100 * 1024);
        attr_set = true;
    }
    int grid = (n + RPI - 1) / RPI;
    gemm_kernel<K, M><<<grid, 256, sh>>>(X, W, out, n);
}

static inline int blocks_for(long long total, int tpb) {
    return (int)((total + tpb - 1) / tpb);
}

extern "C" void kernel_launch(void* const* d_in, const int* in_sizes, int n_in,
                              void* d_out, int out_size) {
    const float* x   = (const float*)d_in[0];
    const int*   ei  = (const int*)d_in[1];   // int32 (JAX default x64-disabled)
    const float* W1 = (const float*)d_in[2];
    const float* b1 = (const float*)d_in[3];
    const float* g1 = (const float*)d_in[4];
    const float* be1= (const float*)d_in[5];
    const float* W2 = (const float*)d_in[6];
    const float* b2 = (const float*)d_in[7];
    const float* g2 = (const float*)d_in[8];
    const float* be2= (const float*)d_in[9];
    const float* W3 = (const float*)d_in[10];
    const float* b3 = (const float*)d_in[11];
    float* out = (float*)d_out;

    int       n = in_sizes[0] / 128;
    long long E = in_sizes[1] / 2;

    float *bufA, *bufB, *dinv, *deg, *stats;
    cudaGetSymbolAddress((void**)&bufA,  g_bufA);
    cudaGetSymbolAddress((void**)&bufB,  g_bufB);
    cudaGetSymbolAddress((void**)&dinv,  g_dinv);
    cudaGetSymbolAddress((void**)&deg,   g_deg);
    cudaGetSymbolAddress((void**)&stats, g_stats);

    // ---- degree / normalization --------------------------------------------
    zero_kernel<<<blocks_for(n, 256), 256>>>(deg, n);
    deg_kernel<<<blocks_for(E, 256), 256>>>(ei, E, deg);
    dinv_kernel<<<blocks_for(n, 256), 256>>>(deg, dinv, n);

    // ---- layer 1: GCNConv(128->128) + BN + ReLU ----------------------------
    launch_gemm<128, 128>(x, W1, bufA, n);
    zero_kernel<<<blocks_for((long long)n * 128, 256), 256>>>(bufB, (long long)n * 128);
    aggregate_kernel<128><<<blocks_for(E * 32, 256), 256>>>(ei, E, bufA, dinv, bufB);
    selfloop_bias_kernel<128><<<blocks_for((long long)n * 128, 256), 256>>>(bufA, dinv, b1, bufB, n);
    zero_kernel<<<1, 256>>>(stats, 256);
    bn_stats_kernel<128><<<512, 256>>>(bufB, n, stats);
    bn_apply_relu_kernel<128><<<blocks_for((long long)n * 128, 256), 256>>>(bufB, n, stats, g1, be1);

    // ---- layer 2: GCNConv(128->64) + BN + ReLU -----------------------------
    launch_gemm<128, 64>(bufB, W2, bufA, n);
    zero_kernel<<<blocks_for((long long)n * 64, 256), 256>>>(bufB, (long long)n * 64);
    aggregate_kernel<64><<<blocks_for(E * 16, 256), 256>>>(ei, E, bufA, dinv, bufB);
    selfloop_bias_kernel<64><<<blocks_for((long long)n * 64, 256), 256>>>(bufA, dinv, b2, bufB, n);
    zero_kernel<<<1, 256>>>(stats, 256);
    bn_stats_kernel<64><<<512, 256>>>(bufB, n, stats);
    bn_apply_relu_kernel<64><<<blocks_for((long long)n * 64, 256), 256>>>(bufB, n, stats, g2, be2);

    // ---- layer 3: GCNConv(64->2) + log_softmax -----------------------------
    launch_gemm<64, 2>(bufB, W3, bufA, n);
    zero_kernel<<<blocks_for((long long)n * 2, 256), 256>>>(bufB, (long long)n * 2);
    aggregate2_kernel<<<blocks_for(E, 256), 256>>>(ei, E, bufA, dinv, bufB);
    selfloop_bias_kernel<2><<<blocks_for((long long)n * 2, 256), 256>>>(bufA, dinv, b3, bufB, n);
    logsoftmax2_kernel<<<blocks_for(n, 256), 256>>>(bufB, out, n);
}

// round 3
// speedup vs baseline: 2.3802x; 2.3802x over previous
#include <cuda_runtime.h>
#include <cuda_bf16.h>
#include <math.h>

// ---------------------------------------------------------------------------
// FraudGNN: 3-layer GCN, N=50000 nodes, E=800000 edges (int32 edge_index).
//   L1: GCNConv(128->128) -> BN -> ReLU
//   L2: GCNConv(128->64)  -> BN -> ReLU
//   L3: GCNConv(64->2)    -> log_softmax
// GCNConv: out = D^{-1/2}(A+I)D^{-1/2} (X W) + b, in-degree incl self-loop.
// R2: register-blocked GEMM, v4 vector red atomics, fused BN stats/apply.
// ---------------------------------------------------------------------------

#define NMAX 50000

__device__ float g_bufA[NMAX * 128];
__device__ float g_bufB[NMAX * 128];
__device__ float g_dinv[NMAX];
__device__ float g_deg[NMAX];
__device__ float g_stats[256];   // [0..127] sum, [128..255] sumsq

// ---------------------------------------------------------------------------
__global__ void deg_kernel(const int* __restrict__ ei, long long E,
                           float* __restrict__ deg) {
    long long e = blockIdx.x * (long long)blockDim.x + threadIdx.x;
    if (e < E) atomicAdd(&deg[ei[E + e]], 1.0f);
}

__global__ void dinv_kernel(const float* __restrict__ deg,
                            float* __restrict__ dinv, int n) {
    int i = blockIdx.x * blockDim.x + threadIdx.x;
    if (i < n) dinv[i] = rsqrtf(deg[i] + 1.0f);   // +1 self-loop
}

// ---------------------------------------------------------------------------
// Register-blocked GEMM: out[n,M] = act(X)[n,K] @ W[K,M].
// 256 threads; each thread computes 4 rows x 8 cols.
// If BN: input transform y = relu((x - m) * g*rsqrt(v+eps) + beta) applied on
// the cooperative load using stats accumulated by the previous pass.
template <int K, int M, bool BN>
__global__ void gemm_rb_kernel(const float* __restrict__ X,
                               const float* __restrict__ W,
                               float* __restrict__ out, int n,
                               const float* __restrict__ stats,
                               const float* __restrict__ g,
                               const float* __restrict__ beta) {
    constexpr int TC   = M / 8;        // thread-cols
    constexpr int TR   = 256 / TC;     // thread-rows
    constexpr int ROWS = TR * 4;       // rows per block

    extern __shared__ float sh[];
    float* Ws     = sh;                    // K*M
    float* xs     = Ws + K * M;            // ROWS*K
    float* sscale = xs + ROWS * K;         // K
    float* sshift = sscale + K;            // K

    const int tid = threadIdx.x;

    if (BN) {
        for (int f = tid; f < K; f += 256) {
            float inv_n = 1.0f / (float)n;
            float m = stats[f] * inv_n;
            float v = stats[128 + f] * inv_n - m * m;
            float sc = g[f] * rsqrtf(v + 1e-5f);
            sscale[f] = sc;
            sshift[f] = beta[f] - m * sc;
        }
        __syncthreads();
    }

    // load W (coalesced float4)
    const float4* W4 = (const float4*)W;
    float4* Ws4 = (float4*)Ws;
    for (int i = tid; i < K * M / 4; i += 256) Ws4[i] = W4[i];

    // cooperative load of ROWS rows of X (float4), with optional BN+ReLU
    const int base = blockIdx.x * ROWS;
    constexpr int K4 = K / 4;
    float4* xs4 = (float4*)xs;
    for (int i = tid; i < ROWS * K4; i += 256) {
        int rr = i / K4, kk = i % K4;
        int row = base + rr;
        float4 v = make_float4(0.f, 0.f, 0.f, 0.f);
        if (row < n) {
            v = *(const float4*)(X + (long long)row * K + kk * 4);
            if (BN) {
                int f = kk * 4;
                v.x = fmaxf(fmaf(v.x, sscale[f + 0], sshift[f + 0]), 0.f);
                v.y = fmaxf(fmaf(v.y, sscale[f + 1], sshift[f + 1]), 0.f);
                v.z = fmaxf(fmaf(v.z, sscale[f + 2], sshift[f + 2]), 0.f);
                v.w = fmaxf(fmaf(v.w, sscale[f + 3], sshift[f + 3]), 0.f);
            }
        }
        xs4[i] = v;
    }
    __syncthreads();

    const int tc = tid % TC;
    const int tr = tid / TC;
    const int c0 = tc * 8;
    const int r0 = tr * 4;

    float acc[4][8];
#pragma unroll
    for (int i = 0; i < 4; i++)
#pragma unroll
        for (int j = 0; j < 8; j++) acc[i][j] = 0.0f;

#pragma unroll 8
    for (int k = 0; k < K; k++) {
        float4 w0 = *(const float4*)&Ws[k * M + c0];
        float4 w1 = *(const float4*)&Ws[k * M + c0 + 4];
        float xv[4];
#pragma unroll
        for (int i = 0; i < 4; i++) xv[i] = xs[(r0 + i) * K + k];
#pragma unroll
        for (int i = 0; i < 4; i++) {
            acc[i][0] = fmaf(xv[i], w0.x, acc[i][0]);
            acc[i][1] = fmaf(xv[i], w0.y, acc[i][1]);
            acc[i][2] = fmaf(xv[i], w0.z, acc[i][2]);
            acc[i][3] = fmaf(xv[i], w0.w, acc[i][3]);
            acc[i][4] = fmaf(xv[i], w1.x, acc[i][4]);
            acc[i][5] = fmaf(xv[i], w1.y, acc[i][5]);
            acc[i][6] = fmaf(xv[i], w1.z, acc[i][6]);
            acc[i][7] = fmaf(xv[i], w1.w, acc[i][7]);
        }
    }

#pragma unroll
    for (int i = 0; i < 4; i++) {
        int row = base + r0 + i;
        if (row < n) {
            float* o = out + (long long)row * M + c0;
            *(float4*)(o)     = make_float4(acc[i][0], acc[i][1], acc[i][2], acc[i][3]);
            *(float4*)(o + 4) = make_float4(acc[i][4], acc[i][5], acc[i][6], acc[i][7]);
        }
    }
}

// Small GEMM for M=2 (layer 3), BN+ReLU fused on load.
template <int K>
__global__ void gemm2_bn_kernel(const float* __restrict__ X,
                                const float* __restrict__ W,
                                float* __restrict__ out, int n,
                                const float* __restrict__ stats,
                                const float* __restrict__ g,
                                const float* __restrict__ beta) {
    __shared__ float Ws[K * 2];
    __shared__ float sscale[K];
    __shared__ float sshift[K];
    __shared__ float xs[128 * K];
    const int tid = threadIdx.x;

    if (tid < K) {
        float inv_n = 1.0f / (float)n;
        float m = stats[tid] * inv_n;
        float v = stats[128 + tid] * inv_n - m * m;
        float sc = g[tid] * rsqrtf(v + 1e-5f);
        sscale[tid] = sc;
        sshift[tid] = beta[tid] - m * sc;
    }
    for (int i = tid; i < K * 2; i += 256) Ws[i] = W[i];
    __syncthreads();

    const int base = blockIdx.x * 128;
    constexpr int K4 = K / 4;
    for (int i = tid; i < 128 * K4; i += 256) {
        int rr = i / K4, kk = i % K4;
        int row = base + rr;
        float4 v = make_float4(0.f, 0.f, 0.f, 0.f);
        if (row < n) {
            v = *(const float4*)(X + (long long)row * K + kk * 4);
            int f = kk * 4;
            v.x = fmaxf(fmaf(v.x, sscale[f + 0], sshift[f + 0]), 0.f);
            v.y = fmaxf(fmaf(v.y, sscale[f + 1], sshift[f + 1]), 0.f);
            v.z = fmaxf(fmaf(v.z, sscale[f + 2], sshift[f + 2]), 0.f);
            v.w = fmaxf(fmaf(v.w, sscale[f + 3], sshift[f + 3]), 0.f);
        }
        *(float4*)&xs[rr * K + kk * 4] = v;
    }
    __syncthreads();

    const int col = tid % 2;
    const int r   = tid / 2;
    int row = base + r;
    if (row < n) {
        float acc = 0.0f;
        const float* xrow = xs + r * K;
#pragma unroll
        for (int k = 0; k < K; k++) acc = fmaf(xrow[k], Ws[k * 2 + col], acc);
        out[(long long)row * 2 + col] = acc;
    }
}

// ---------------------------------------------------------------------------
// Edge aggregation: out[dst] += h[src] * dinv[src]*dinv[dst].
// F/4 threads per edge; one vectorized red.v4 per thread.
template <int F>
__global__ void aggregate_kernel(const int* __restrict__ ei, long long E,
                                 const float* __restrict__ h,
                                 const float* __restrict__ dinv,
                                 float* __restrict__ out) {
    constexpr int C4 = F / 4;
    long long tid = blockIdx.x * (long long)blockDim.x + threadIdx.x;
    long long e = tid / C4;
    int c = (int)(tid % C4);
    if (e >= E) return;
    int s = ei[e];
    int d = ei[E + e];
    float norm = dinv[s] * dinv[d];
    float4 v = *(const float4*)(h + (long long)s * F + c * 4);
    float* o = out + (long long)d * F + c * 4;
    asm volatile("red.global.add.v4.f32 [%0], {%1, %2, %3, %4};"
                 :: "l"(o), "f"(v.x * norm), "f"(v.y * norm),
                    "f"(v.z * norm), "f"(v.w * norm)
                 : "memory");
}

// F == 2: one thread per edge, two scalar reds.
__global__ void aggregate2_kernel(const int* __restrict__ ei, long long E,
                                  const float* __restrict__ h,
                                  const float* __restrict__ dinv,
                                  float* __restrict__ out) {
    long long e = blockIdx.x * (long long)blockDim.x + threadIdx.x;
    if (e >= E) return;
    int s = ei[e];
    int d = ei[E + e];
    float norm = dinv[s] * dinv[d];
    float2 v = *(const float2*)(h + (long long)s * 2);
    atomicAdd(out + (long long)d * 2 + 0, v.x * norm);
    atomicAdd(out + (long long)d * 2 + 1, v.y * norm);
}

// ---------------------------------------------------------------------------
// Fused: out[v,f] += h[v,f]*dinv[v]^2 + b[f], and accumulate BN sum/sumsq.
// Grid-stride with stride % F == 0 -> each thread owns a fixed feature f.
template <int F>
__global__ void selfloop_bias_stats_kernel(const float* __restrict__ h,
                                           const float* __restrict__ dinv,
                                           const float* __restrict__ b,
                                           float* __restrict__ out, int n,
                                           float* __restrict__ stats) {
    long long total = (long long)n * F;
    long long stride = (long long)gridDim.x * blockDim.x;   // multiple of F
    int f = (int)((blockIdx.x * (long long)blockDim.x + threadIdx.x) % F);
    float bias = b[f];
    float lsum = 0.f, lsq = 0.f;
    for (long long i = blockIdx.x * (long long)blockDim.x + threadIdx.x;
         i < total; i += stride) {
        int node = (int)(i / F);
        float dv = dinv[node];
        float val = out[i] + h[i] * dv * dv + bias;
        out[i] = val;
        lsum += val;
        lsq  = fmaf(val, val, lsq);
    }
    atomicAdd(&stats[f], lsum);
    atomicAdd(&stats[128 + f], lsq);
}

// L3 tail: out2[v] = log_softmax(agg[v] + h[v]*dinv^2 + b).
__global__ void selfloop_logsoftmax_kernel(const float* __restrict__ h,
                                           const float* __restrict__ dinv,
                                           const float* __restrict__ b,
                                           const float* __restrict__ agg,
                                           float* __restrict__ out, int n) {
    int i = blockIdx.x * blockDim.x + threadIdx.x;
    if (i >= n) return;
    float dv = dinv[i];
    float d2 = dv * dv;
    float a = agg[2 * i]     + h[2 * i]     * d2 + b[0];
    float c = agg[2 * i + 1] + h[2 * i + 1] * d2 + b[1];
    float m = fmaxf(a, c);
    float l = m + logf(expf(a - m) + expf(c - m));
    out[2 * i]     = a - l;
    out[2 * i + 1] = c - l;
}

// ---------------------------------------------------------------------------
static inline int blocks_for(long long total, int tpb) {
    return (int)((total + tpb - 1) / tpb);
}

template <int K, int M, bool BN>
static void launch_gemm_rb(const float* X, const float* W, float* out, int n,
                           const float* stats, const float* g, const float* beta) {
    constexpr int TC = M / 8;
    constexpr int TR = 256 / TC;
    constexpr int ROWS = TR * 4;
    size_t sh = (size_t)(K * M + ROWS * K + 2 * K) * sizeof(float);
    cudaFuncSetAttribute(gemm_rb_kernel<K, M, BN>,
                         cudaFuncAttributeMaxDynamicSharedMemorySize, (int)sh);
    int grid = (n + ROWS - 1) / ROWS;
    gemm_rb_kernel<K, M, BN><<<grid, 256, sh>>>(X, W, out, n, stats, g, beta);
}

extern "C" void kernel_launch(void* const* d_in, const int* in_sizes, int n_in,
                              void* d_out, int out_size) {
    const float* x   = (const float*)d_in[0];
    const int*   ei  = (const int*)d_in[1];
    const float* W1 = (const float*)d_in[2];
    const float* b1 = (const float*)d_in[3];
    const float* g1 = (const float*)d_in[4];
    const float* be1= (const float*)d_in[5];
    const float* W2 = (const float*)d_in[6];
    const float* b2 = (const float*)d_in[7];
    const float* g2 = (const float*)d_in[8];
    const float* be2= (const float*)d_in[9];
    const float* W3 = (const float*)d_in[10];
    const float* b3 = (const float*)d_in[11];
    float* out = (float*)d_out;

    int       n = in_sizes[0] / 128;
    long long E = in_sizes[1] / 2;

    float *bufA, *bufB, *dinv, *deg, *stats;
    cudaGetSymbolAddress((void**)&bufA,  g_bufA);
    cudaGetSymbolAddress((void**)&bufB,  g_bufB);
    cudaGetSymbolAddress((void**)&dinv,  g_dinv);
    cudaGetSymbolAddress((void**)&deg,   g_deg);
    cudaGetSymbolAddress((void**)&stats, g_stats);

    // ---- degree / normalization --------------------------------------------
    cudaMemsetAsync(deg, 0, (size_t)n * sizeof(float));
    deg_kernel<<<blocks_for(E, 256), 256>>>(ei, E, deg);
    dinv_kernel<<<blocks_for(n, 256), 256>>>(deg, dinv, n);

    // ---- layer 1: GCNConv(128->128), stats for BN1 --------------------------
    launch_gemm_rb<128, 128, false>(x, W1, bufA, n, nullptr, nullptr, nullptr);
    cudaMemsetAsync(bufB, 0, (size_t)n * 128 * sizeof(float));
    aggregate_kernel<128><<<blocks_for(E * 32, 256), 256>>>(ei, E, bufA, dinv, bufB);
    cudaMemsetAsync(stats, 0, 256 * sizeof(float));
    selfloop_bias_stats_kernel<128><<<400, 256>>>(bufA, dinv, b1, bufB, n, stats);

    // ---- layer 2: BN1+ReLU fused into GEMM(128->64), stats for BN2 ----------
    launch_gemm_rb<128, 64, true>(bufB, W2, bufA, n, stats, g1, be1);
    cudaMemsetAsync(bufB, 0, (size_t)n * 64 * sizeof(float));
    aggregate_kernel<64><<<blocks_for(E * 16, 256), 256>>>(ei, E, bufA, dinv, bufB);
    cudaMemsetAsync(stats, 0, 256 * sizeof(float));
    selfloop_bias_stats_kernel<64><<<400, 256>>>(bufA, dinv, b2, bufB, n, stats);

    // ---- layer 3: BN2+ReLU fused into GEMM(64->2), log_softmax --------------
    gemm2_bn_kernel<64><<<blocks_for(n, 128), 256>>>(bufB, W3, bufA, n, stats, g2, be2);
    cudaMemsetAsync(bufB, 0, (size_t)n * 2 * sizeof(float));
    aggregate2_kernel<<<blocks_for(E, 256), 256>>>(ei, E, bufA, dinv, bufB);
    selfloop_logsoftmax_kernel<<<blocks_for(n, 256), 256>>>(bufA, dinv, b3, bufB, out, n);
}

// round 5
// speedup vs baseline: 2.6565x; 1.1161x over previous
#include <cuda_runtime.h>
#include <cuda_bf16.h>
#include <math.h>

// ---------------------------------------------------------------------------
// FraudGNN: 3-layer GCN, N=50000 nodes, E=800000 edges (int32 edge_index).
// R4 (= R3 resubmit; container infra failure): CSR pull-aggregation (no float
// atomics), fused self-loop/bias/BN-stats, fused log_softmax tail. BN
// apply+ReLU fused into next GEMM load.
// ---------------------------------------------------------------------------

#define NMAX 50000
#define EMAX 800000

__device__ float g_bufA[NMAX * 128];
__device__ float g_bufB[NMAX * 128];
__device__ float g_dinv[NMAX];
__device__ float g_stats[256];        // [0..127] sum, [128..255] sumsq
__device__ int   g_counts[NMAX];
__device__ int   g_offsets[NMAX + 1];
__device__ int   g_cursor[NMAX];
__device__ int   g_csr_src[EMAX];

// ---------------------------------------------------------------------------
__global__ void hist_kernel(const int* __restrict__ ei, long long E,
                            int* __restrict__ counts) {
    long long e = blockIdx.x * (long long)blockDim.x + threadIdx.x;
    if (e < E) atomicAdd(&counts[ei[E + e]], 1);
}

// Single-block exclusive scan over counts -> offsets; also dinv = rsqrt(deg+1).
__global__ void scan_kernel(const int* __restrict__ counts,
                            int* __restrict__ offsets,
                            float* __restrict__ dinv, int n) {
    __shared__ int partial[1024];
    const int t = threadIdx.x;
    const int chunk = (n + 1023) / 1024;
    const int begin = t * chunk;
    const int end = min(begin + chunk, n);
    int s = 0;
    for (int i = begin; i < end; i++) s += counts[i];
    partial[t] = s;
    __syncthreads();
    // Hillis-Steele inclusive scan
    for (int off = 1; off < 1024; off <<= 1) {
        int x = (t >= off) ? partial[t - off] : 0;
        __syncthreads();
        partial[t] += x;
        __syncthreads();
    }
    int running = partial[t] - s;   // exclusive prefix for this chunk
    for (int i = begin; i < end; i++) {
        offsets[i] = running;
        int c = counts[i];
        running += c;
        dinv[i] = rsqrtf((float)c + 1.0f);
    }
    if (t == 1023) offsets[n] = partial[1023];
}

__global__ void scatter_kernel(const int* __restrict__ ei, long long E,
                               int* __restrict__ cursor,
                               int* __restrict__ csr_src) {
    long long e = blockIdx.x * (long long)blockDim.x + threadIdx.x;
    if (e < E) {
        int s = ei[e];
        int d = ei[E + e];
        int pos = atomicAdd(&cursor[d], 1);
        csr_src[pos] = s;
    }
}

// ---------------------------------------------------------------------------
// Register-blocked GEMM: out[n,M] = act(X)[n,K] @ W[K,M].
// 256 threads; each thread computes 4 rows x 8 cols.
// If BN: y = relu((x-m)*g*rsqrt(v+eps)+beta) applied on the cooperative load.
template <int K, int M, bool BN>
__global__ void gemm_rb_kernel(const float* __restrict__ X,
                               const float* __restrict__ W,
                               float* __restrict__ out, int n,
                               const float* __restrict__ stats,
                               const float* __restrict__ g,
                               const float* __restrict__ beta) {
    constexpr int TC   = M / 8;
    constexpr int TR   = 256 / TC;
    constexpr int ROWS = TR * 4;

    extern __shared__ float sh[];
    float* Ws     = sh;                    // K*M
    float* xs     = Ws + K * M;            // ROWS*K
    float* sscale = xs + ROWS * K;         // K
    float* sshift = sscale + K;            // K

    const int tid = threadIdx.x;

    if (BN) {
        for (int f = tid; f < K; f += 256) {
            float inv_n = 1.0f / (float)n;
            float m = stats[f] * inv_n;
            float v = stats[128 + f] * inv_n - m * m;
            float sc = g[f] * rsqrtf(v + 1e-5f);
            sscale[f] = sc;
            sshift[f] = beta[f] - m * sc;
        }
        __syncthreads();
    }

    const float4* W4 = (const float4*)W;
    float4* Ws4 = (float4*)Ws;
    for (int i = tid; i < K * M / 4; i += 256) Ws4[i] = W4[i];

    const int base = blockIdx.x * ROWS;
    constexpr int K4 = K / 4;
    float4* xs4 = (float4*)xs;
    for (int i = tid; i < ROWS * K4; i += 256) {
        int rr = i / K4, kk = i % K4;
        int row = base + rr;
        float4 v = make_float4(0.f, 0.f, 0.f, 0.f);
        if (row < n) {
            v = *(const float4*)(X + (long long)row * K + kk * 4);
            if (BN) {
                int f = kk * 4;
                v.x = fmaxf(fmaf(v.x, sscale[f + 0], sshift[f + 0]), 0.f);
                v.y = fmaxf(fmaf(v.y, sscale[f + 1], sshift[f + 1]), 0.f);
                v.z = fmaxf(fmaf(v.z, sscale[f + 2], sshift[f + 2]), 0.f);
                v.w = fmaxf(fmaf(v.w, sscale[f + 3], sshift[f + 3]), 0.f);
            }
        }
        xs4[i] = v;
    }
    __syncthreads();

    const int tc = tid % TC;
    const int tr = tid / TC;
    const int c0 = tc * 8;
    const int r0 = tr * 4;

    float acc[4][8];
#pragma unroll
    for (int i = 0; i < 4; i++)
#pragma unroll
        for (int j = 0; j < 8; j++) acc[i][j] = 0.0f;

#pragma unroll 8
    for (int k = 0; k < K; k++) {
        float4 w0 = *(const float4*)&Ws[k * M + c0];
        float4 w1 = *(const float4*)&Ws[k * M + c0 + 4];
        float xv[4];
#pragma unroll
        for (int i = 0; i < 4; i++) xv[i] = xs[(r0 + i) * K + k];
#pragma unroll
        for (int i = 0; i < 4; i++) {
            acc[i][0] = fmaf(xv[i], w0.x, acc[i][0]);
            acc[i][1] = fmaf(xv[i], w0.y, acc[i][1]);
            acc[i][2] = fmaf(xv[i], w0.z, acc[i][2]);
            acc[i][3] = fmaf(xv[i], w0.w, acc[i][3]);
            acc[i][4] = fmaf(xv[i], w1.x, acc[i][4]);
            acc[i][5] = fmaf(xv[i], w1.y, acc[i][5]);
            acc[i][6] = fmaf(xv[i], w1.z, acc[i][6]);
            acc[i][7] = fmaf(xv[i], w1.w, acc[i][7]);
        }
    }

#pragma unroll
    for (int i = 0; i < 4; i++) {
        int row = base + r0 + i;
        if (row < n) {
            float* o = out + (long long)row * M + c0;
            *(float4*)(o)     = make_float4(acc[i][0], acc[i][1], acc[i][2], acc[i][3]);
            *(float4*)(o + 4) = make_float4(acc[i][4], acc[i][5], acc[i][6], acc[i][7]);
        }
    }
}

// Small GEMM for M=2 (layer 3), BN+ReLU fused on load.
template <int K>
__global__ void gemm2_bn_kernel(const float* __restrict__ X,
                                const float* __restrict__ W,
                                float* __restrict__ out, int n,
                                const float* __restrict__ stats,
                                const float* __restrict__ g,
                                const float* __restrict__ beta) {
    __shared__ float Ws[K * 2];
    __shared__ float sscale[K];
    __shared__ float sshift[K];
    __shared__ float xs[128 * K];
    const int tid = threadIdx.x;

    if (tid < K) {
        float inv_n = 1.0f / (float)n;
        float m = stats[tid] * inv_n;
        float v = stats[128 + tid] * inv_n - m * m;
        float sc = g[tid] * rsqrtf(v + 1e-5f);
        sscale[tid] = sc;
        sshift[tid] = beta[tid] - m * sc;
    }
    for (int i = tid; i < K * 2; i += 256) Ws[i] = W[i];
    __syncthreads();

    const int base = blockIdx.x * 128;
    constexpr int K4 = K / 4;
    for (int i = tid; i < 128 * K4; i += 256) {
        int rr = i / K4, kk = i % K4;
        int row = base + rr;
        float4 v = make_float4(0.f, 0.f, 0.f, 0.f);
        if (row < n) {
            v = *(const float4*)(X + (long long)row * K + kk * 4);
            int f = kk * 4;
            v.x = fmaxf(fmaf(v.x, sscale[f + 0], sshift[f + 0]), 0.f);
            v.y = fmaxf(fmaf(v.y, sscale[f + 1], sshift[f + 1]), 0.f);
            v.z = fmaxf(fmaf(v.z, sscale[f + 2], sshift[f + 2]), 0.f);
            v.w = fmaxf(fmaf(v.w, sscale[f + 3], sshift[f + 3]), 0.f);
        }
        *(float4*)&xs[rr * K + kk * 4] = v;
    }
    __syncthreads();

    const int col = tid % 2;
    const int r   = tid / 2;
    int row = base + r;
    if (row < n) {
        float acc = 0.0f;
        const float* xrow = xs + r * K;
#pragma unroll
        for (int k = 0; k < K; k++) acc = fmaf(xrow[k], Ws[k * 2 + col], acc);
        out[(long long)row * 2 + col] = acc;
    }
}

// ---------------------------------------------------------------------------
// CSR pull-aggregation, F=128. Warp per node (grid-stride), lane owns 4
// features. Fuses self-loop + bias + BN stats accumulation.
__global__ void __launch_bounds__(256)
csr_agg128_kernel(const int* __restrict__ csr_src,
                  const int* __restrict__ offsets,
                  const float* __restrict__ h,
                  const float* __restrict__ dinv,
                  const float* __restrict__ b,
                  float* __restrict__ out, int n,
                  float* __restrict__ stats) {
    __shared__ float ssum[128];
    __shared__ float ssq[128];
    const int tid  = threadIdx.x;
    const int lane = tid & 31;
    const int wid  = tid >> 5;
    if (tid < 128) { ssum[tid] = 0.f; ssq[tid] = 0.f; }
    __syncthreads();

    const float4* h4 = (const float4*)h;
    float4* out4 = (float4*)out;
    float4 bv = ((const float4*)b)[lane];

    float4 lsum = make_float4(0.f, 0.f, 0.f, 0.f);
    float4 lsq  = make_float4(0.f, 0.f, 0.f, 0.f);

    for (int node = blockIdx.x * 8 + wid; node < n; node += gridDim.x * 8) {
        const int e0 = offsets[node];
        const int e1 = offsets[node + 1];
        const float dn = dinv[node];
        float4 acc = make_float4(0.f, 0.f, 0.f, 0.f);

        int j = e0;
        for (; j + 4 <= e1; j += 4) {
            int sa = csr_src[j],     sb = csr_src[j + 1];
            int sc = csr_src[j + 2], sd = csr_src[j + 3];
            float na = dinv[sa] * dn, nb = dinv[sb] * dn;
            float nc = dinv[sc] * dn, nd = dinv[sd] * dn;
            float4 va = h4[(long long)sa * 32 + lane];
            float4 vb = h4[(long long)sb * 32 + lane];
            float4 vc = h4[(long long)sc * 32 + lane];
            float4 vd = h4[(long long)sd * 32 + lane];
            acc.x += va.x * na + vb.x * nb + vc.x * nc + vd.x * nd;
            acc.y += va.y * na + vb.y * nb + vc.y * nc + vd.y * nd;
            acc.z += va.z * na + vb.z * nb + vc.z * nc + vd.z * nd;
            acc.w += va.w * na + vb.w * nb + vc.w * nc + vd.w * nd;
        }
        for (; j < e1; j++) {
            int s = csr_src[j];
            float nm = dinv[s] * dn;
            float4 v = h4[(long long)s * 32 + lane];
            acc.x += v.x * nm; acc.y += v.y * nm;
            acc.z += v.z * nm; acc.w += v.w * nm;
        }
        // self-loop + bias
        float4 hv = h4[(long long)node * 32 + lane];
        float d2 = dn * dn;
        acc.x = fmaf(hv.x, d2, acc.x) + bv.x;
        acc.y = fmaf(hv.y, d2, acc.y) + bv.y;
        acc.z = fmaf(hv.z, d2, acc.z) + bv.z;
        acc.w = fmaf(hv.w, d2, acc.w) + bv.w;
        out4[(long long)node * 32 + lane] = acc;

        lsum.x += acc.x; lsum.y += acc.y; lsum.z += acc.z; lsum.w += acc.w;
        lsq.x = fmaf(acc.x, acc.x, lsq.x); lsq.y = fmaf(acc.y, acc.y, lsq.y);
        lsq.z = fmaf(acc.z, acc.z, lsq.z); lsq.w = fmaf(acc.w, acc.w, lsq.w);
    }

    atomicAdd(&ssum[lane * 4 + 0], lsum.x);
    atomicAdd(&ssum[lane * 4 + 1], lsum.y);
    atomicAdd(&ssum[lane * 4 + 2], lsum.z);
    atomicAdd(&ssum[lane * 4 + 3], lsum.w);
    atomicAdd(&ssq[lane * 4 + 0], lsq.x);
    atomicAdd(&ssq[lane * 4 + 1], lsq.y);
    atomicAdd(&ssq[lane * 4 + 2], lsq.z);
    atomicAdd(&ssq[lane * 4 + 3], lsq.w);
    __syncthreads();
    if (tid < 128) {
        atomicAdd(&stats[tid], ssum[tid]);
        atomicAdd(&stats[128 + tid], ssq[tid]);
    }
}

// F=64 version: lane owns 2 features (float2).
__global__ void __launch_bounds__(256)
csr_agg64_kernel(const int* __restrict__ csr_src,
                 const int* __restrict__ offsets,
                 const float* __restrict__ h,
                 const float* __restrict__ dinv,
                 const float* __restrict__ b,
                 float* __restrict__ out, int n,
                 float* __restrict__ stats) {
    __shared__ float ssum[64];
    __shared__ float ssq[64];
    const int tid  = threadIdx.x;
    const int lane = tid & 31;
    const int wid  = tid >> 5;
    if (tid < 64) { ssum[tid] = 0.f; ssq[tid] = 0.f; }
    __syncthreads();

    const float2* h2 = (const float2*)h;
    float2* out2 = (float2*)out;
    float2 bv = ((const float2*)b)[lane];

    float2 lsum = make_float2(0.f, 0.f);
    float2 lsq  = make_float2(0.f, 0.f);

    for (int node = blockIdx.x * 8 + wid; node < n; node += gridDim.x * 8) {
        const int e0 = offsets[node];
        const int e1 = offsets[node + 1];
        const float dn = dinv[node];
        float2 acc = make_float2(0.f, 0.f);

        int j = e0;
        for (; j + 4 <= e1; j += 4) {
            int sa = csr_src[j],     sb = csr_src[j + 1];
            int sc = csr_src[j + 2], sd = csr_src[j + 3];
            float na = dinv[sa] * dn, nb = dinv[sb] * dn;
            float nc = dinv[sc] * dn, nd = dinv[sd] * dn;
            float2 va = h2[(long long)sa * 32 + lane];
            float2 vb = h2[(long long)sb * 32 + lane];
            float2 vc = h2[(long long)sc * 32 + lane];
            float2 vd = h2[(long long)sd * 32 + lane];
            acc.x += va.x * na + vb.x * nb + vc.x * nc + vd.x * nd;
            acc.y += va.y * na + vb.y * nb + vc.y * nc + vd.y * nd;
        }
        for (; j < e1; j++) {
            int s = csr_src[j];
            float nm = dinv[s] * dn;
            float2 v = h2[(long long)s * 32 + lane];
            acc.x += v.x * nm; acc.y += v.y * nm;
        }
        float2 hv = h2[(long long)node * 32 + lane];
        float d2 = dn * dn;
        acc.x = fmaf(hv.x, d2, acc.x) + bv.x;
        acc.y = fmaf(hv.y, d2, acc.y) + bv.y;
        out2[(long long)node * 32 + lane] = acc;

        lsum.x += acc.x; lsum.y += acc.y;
        lsq.x = fmaf(acc.x, acc.x, lsq.x);
        lsq.y = fmaf(acc.y, acc.y, lsq.y);
    }

    atomicAdd(&ssum[lane * 2 + 0], lsum.x);
    atomicAdd(&ssum[lane * 2 + 1], lsum.y);
    atomicAdd(&ssq[lane * 2 + 0], lsq.x);
    atomicAdd(&ssq[lane * 2 + 1], lsq.y);
    __syncthreads();
    if (tid < 64) {
        atomicAdd(&stats[tid], ssum[tid]);
        atomicAdd(&stats[128 + tid], ssq[tid]);
    }
}

// F=2: thread per node; fuses self-loop + bias + log_softmax, writes d_out.
__global__ void __launch_bounds__(256)
csr_agg2_lsm_kernel(const int* __restrict__ csr_src,
                    const int* __restrict__ offsets,
                    const float* __restrict__ h,
                    const float* __restrict__ dinv,
                    const float* __restrict__ b,
                    float* __restrict__ out, int n) {
    int node = blockIdx.x * blockDim.x + threadIdx.x;
    if (node >= n) return;
    const float2* h2 = (const float2*)h;
    const int e0 = offsets[node];
    const int e1 = offsets[node + 1];
    const float dn = dinv[node];
    float ax = 0.f, ay = 0.f;
    int j = e0;
    for (; j + 4 <= e1; j += 4) {
        int sa = csr_src[j],     sb = csr_src[j + 1];
        int sc = csr_src[j + 2], sd = csr_src[j + 3];
        float na = dinv[sa] * dn, nb = dinv[sb] * dn;
        float nc = dinv[sc] * dn, nd = dinv[sd] * dn;
        float2 va = h2[sa], vb = h2[sb], vc = h2[sc], vd = h2[sd];
        ax += va.x * na + vb.x * nb + vc.x * nc + vd.x * nd;
        ay += va.y * na + vb.y * nb + vc.y * nc + vd.y * nd;
    }
    for (; j < e1; j++) {
        int s = csr_src[j];
        float nm = dinv[s] * dn;
        float2 v = h2[s];
        ax += v.x * nm; ay += v.y * nm;
    }
    float2 hv = h2[node];
    float d2 = dn * dn;
    float a = fmaf(hv.x, d2, ax) + b[0];
    float c = fmaf(hv.y, d2, ay) + b[1];
    float m = fmaxf(a, c);
    float l = m + logf(expf(a - m) + expf(c - m));
    out[2 * node]     = a - l;
    out[2 * node + 1] = c - l;
}

// ---------------------------------------------------------------------------
static inline int blocks_for(long long total, int tpb) {
    return (int)((total + tpb - 1) / tpb);
}

template <int K, int M, bool BN>
static void launch_gemm_rb(const float* X, const float* W, float* out, int n,
                           const float* stats, const float* g, const float* beta) {
    constexpr int TC = M / 8;
    constexpr int TR = 256 / TC;
    constexpr int ROWS = TR * 4;
    size_t sh = (size_t)(K * M + ROWS * K + 2 * K) * sizeof(float);
    cudaFuncSetAttribute(gemm_rb_kernel<K, M, BN>,
                         cudaFuncAttributeMaxDynamicSharedMemorySize, (int)sh);
    int grid = (n + ROWS - 1) / ROWS;
    gemm_rb_kernel<K, M, BN><<<grid, 256, sh>>>(X, W, out, n, stats, g, beta);
}

extern "C" void kernel_launch(void* const* d_in, const int* in_sizes, int n_in,
                              void* d_out, int out_size) {
    const float* x   = (const float*)d_in[0];
    const int*   ei  = (const int*)d_in[1];
    const float* W1 = (const float*)d_in[2];
    const float* b1 = (const float*)d_in[3];
    const float* g1 = (const float*)d_in[4];
    const float* be1= (const float*)d_in[5];
    const float* W2 = (const float*)d_in[6];
    const float* b2 = (const float*)d_in[7];
    const float* g2 = (const float*)d_in[8];
    const float* be2= (const float*)d_in[9];
    const float* W3 = (const float*)d_in[10];
    const float* b3 = (const float*)d_in[11];
    float* out = (float*)d_out;

    int       n = in_sizes[0] / 128;
    long long E = in_sizes[1] / 2;

    float *bufA, *bufB, *dinv, *stats;
    int *counts, *offsets, *cursor, *csr_src;
    cudaGetSymbolAddress((void**)&bufA,    g_bufA);
    cudaGetSymbolAddress((void**)&bufB,    g_bufB);
    cudaGetSymbolAddress((void**)&dinv,    g_dinv);
    cudaGetSymbolAddress((void**)&stats,   g_stats);
    cudaGetSymbolAddress((void**)&counts,  g_counts);
    cudaGetSymbolAddress((void**)&offsets, g_offsets);
    cudaGetSymbolAddress((void**)&cursor,  g_cursor);
    cudaGetSymbolAddress((void**)&csr_src, g_csr_src);

    const int AGG_GRID = 1184;   // 8 warps/block, grid-stride over nodes

    // ---- CSR build + dinv ---------------------------------------------------
    cudaMemsetAsync(counts, 0, (size_t)n * sizeof(int));
    hist_kernel<<<blocks_for(E, 256), 256>>>(ei, E, counts);
    scan_kernel<<<1, 1024>>>(counts, offsets, dinv, n);
    cudaMemcpyAsync(cursor, offsets, (size_t)n * sizeof(int),
                    cudaMemcpyDeviceToDevice);
    scatter_kernel<<<blocks_for(E, 256), 256>>>(ei, E, cursor, csr_src);

    // ---- layer 1: GCNConv(128->128) + stats ---------------------------------
    launch_gemm_rb<128, 128, false>(x, W1, bufA, n, nullptr, nullptr, nullptr);
    cudaMemsetAsync(stats, 0, 256 * sizeof(float));
    csr_agg128_kernel<<<AGG_GRID, 256>>>(csr_src, offsets, bufA, dinv, b1,
                                         bufB, n, stats);

    // ---- layer 2: BN1+ReLU fused GEMM(128->64) + stats ----------------------
    launch_gemm_rb<128, 64, true>(bufB, W2, bufA, n, stats, g1, be1);
    cudaMemsetAsync(stats, 0, 256 * sizeof(float));
    csr_agg64_kernel<<<AGG_GRID, 256>>>(csr_src, offsets, bufA, dinv, b2,
                                        bufB, n, stats);

    // ---- layer 3: BN2+ReLU fused GEMM(64->2) + agg + log_softmax ------------
    gemm2_bn_kernel<64><<<blocks_for(n, 128), 256>>>(bufB, W3, bufA, n,
                                                     stats, g2, be2);
    csr_agg2_lsm_kernel<<<blocks_for(n, 256), 256>>>(csr_src, offsets, bufA,
                                                     dinv, b3, out, n);
}

// round 6
// speedup vs baseline: 3.1288x; 1.1778x over previous
#include <cuda_runtime.h>
#include <cuda_bf16.h>
#include <math.h>

// ---------------------------------------------------------------------------
// FraudGNN: 3-layer GCN, N=50000 nodes, E=800000 edges (int32 edge_index).
// R6: GEMM reads W via __ldg (L1-resident, no smem stage) -> 3 blocks/SM;
//     k-unroll x4 with float4 x loads; CSR build overlapped on side stream.
// ---------------------------------------------------------------------------

#define NMAX 50000
#define EMAX 800000

__device__ float g_bufA[NMAX * 128];
__device__ float g_bufB[NMAX * 128];
__device__ float g_dinv[NMAX];
__device__ float g_stats[256];        // [0..127] sum, [128..255] sumsq
__device__ int   g_counts[NMAX];
__device__ int   g_offsets[NMAX + 1];
__device__ int   g_cursor[NMAX];
__device__ int   g_csr_src[EMAX];

// ---------------------------------------------------------------------------
__global__ void hist_kernel(const int* __restrict__ ei, long long E,
                            int* __restrict__ counts) {
    long long e = blockIdx.x * (long long)blockDim.x + threadIdx.x;
    if (e < E) atomicAdd(&counts[ei[E + e]], 1);
}

// Single-block exclusive scan over counts -> offsets; also dinv = rsqrt(deg+1).
__global__ void scan_kernel(const int* __restrict__ counts,
                            int* __restrict__ offsets,
                            float* __restrict__ dinv, int n) {
    __shared__ int partial[1024];
    const int t = threadIdx.x;
    const int chunk = (n + 1023) / 1024;
    const int begin = t * chunk;
    const int end = min(begin + chunk, n);
    int s = 0;
#pragma unroll 4
    for (int i = begin; i < end; i++) s += counts[i];
    partial[t] = s;
    __syncthreads();
    for (int off = 1; off < 1024; off <<= 1) {
        int x = (t >= off) ? partial[t - off] : 0;
        __syncthreads();
        partial[t] += x;
        __syncthreads();
    }
    int running = partial[t] - s;   // exclusive prefix for this chunk
    for (int i = begin; i < end; i++) {
        offsets[i] = running;
        int c = counts[i];
        running += c;
        dinv[i] = rsqrtf((float)c + 1.0f);
    }
    if (t == 1023) offsets[n] = partial[1023];
}

__global__ void scatter_kernel(const int* __restrict__ ei, long long E,
                               int* __restrict__ cursor,
                               int* __restrict__ csr_src) {
    long long e = blockIdx.x * (long long)blockDim.x + threadIdx.x;
    if (e < E) {
        int s = ei[e];
        int d = ei[E + e];
        int pos = atomicAdd(&cursor[d], 1);
        csr_src[pos] = s;
    }
}

// ---------------------------------------------------------------------------
// Register-blocked GEMM: out[n,M] = act(X)[n,K] @ W[K,M].
// 256 threads; thread tile 4 rows x 8 cols. X staged in smem (with optional
// BN+ReLU transform); W read via __ldg (identical across blocks -> L1/L2).
template <int K, int M, bool BN>
__global__ void __launch_bounds__(256, 3)
gemm_rb_kernel(const float* __restrict__ X,
               const float* __restrict__ W,
               float* __restrict__ out, int n,
               const float* __restrict__ stats,
               const float* __restrict__ g,
               const float* __restrict__ beta) {
    constexpr int TC   = M / 8;
    constexpr int TR   = 256 / TC;
    constexpr int ROWS = TR * 4;

    extern __shared__ float sh[];
    float* xs     = sh;                    // ROWS*K
    float* sscale = xs + ROWS * K;         // K
    float* sshift = sscale + K;            // K

    const int tid = threadIdx.x;

    if (BN) {
        for (int f = tid; f < K; f += 256) {
            float inv_n = 1.0f / (float)n;
            float m = stats[f] * inv_n;
            float v = stats[128 + f] * inv_n - m * m;
            float sc = g[f] * rsqrtf(v + 1e-5f);
            sscale[f] = sc;
            sshift[f] = beta[f] - m * sc;
        }
        __syncthreads();
    }

    const int base = blockIdx.x * ROWS;
    constexpr int K4 = K / 4;
    float4* xs4 = (float4*)xs;
    for (int i = tid; i < ROWS * K4; i += 256) {
        int rr = i / K4, kk = i % K4;
        int row = base + rr;
        float4 v = make_float4(0.f, 0.f, 0.f, 0.f);
        if (row < n) {
            v = *(const float4*)(X + (long long)row * K + kk * 4);
            if (BN) {
                int f = kk * 4;
                v.x = fmaxf(fmaf(v.x, sscale[f + 0], sshift[f + 0]), 0.f);
                v.y = fmaxf(fmaf(v.y, sscale[f + 1], sshift[f + 1]), 0.f);
                v.z = fmaxf(fmaf(v.z, sscale[f + 2], sshift[f + 2]), 0.f);
                v.w = fmaxf(fmaf(v.w, sscale[f + 3], sshift[f + 3]), 0.f);
            }
        }
        xs4[i] = v;
    }
    __syncthreads();

    const int tc = tid % TC;
    const int tr = tid / TC;
    const int c0 = tc * 8;
    const int r0 = tr * 4;

    float acc[4][8];
#pragma unroll
    for (int i = 0; i < 4; i++)
#pragma unroll
        for (int j = 0; j < 8; j++) acc[i][j] = 0.0f;

    for (int k0 = 0; k0 < K; k0 += 4) {
        float4 xv[4];
#pragma unroll
        for (int i = 0; i < 4; i++)
            xv[i] = *(const float4*)&xs[(r0 + i) * K + k0];
#pragma unroll
        for (int kk = 0; kk < 4; kk++) {
            const float4 w0 = __ldg((const float4*)&W[(k0 + kk) * M + c0]);
            const float4 w1 = __ldg((const float4*)&W[(k0 + kk) * M + c0 + 4]);
#pragma unroll
            for (int i = 0; i < 4; i++) {
                float xvi = (kk == 0) ? xv[i].x :
                            (kk == 1) ? xv[i].y :
                            (kk == 2) ? xv[i].z : xv[i].w;
                acc[i][0] = fmaf(xvi, w0.x, acc[i][0]);
                acc[i][1] = fmaf(xvi, w0.y, acc[i][1]);
                acc[i][2] = fmaf(xvi, w0.z, acc[i][2]);
                acc[i][3] = fmaf(xvi, w0.w, acc[i][3]);
                acc[i][4] = fmaf(xvi, w1.x, acc[i][4]);
                acc[i][5] = fmaf(xvi, w1.y, acc[i][5]);
                acc[i][6] = fmaf(xvi, w1.z, acc[i][6]);
                acc[i][7] = fmaf(xvi, w1.w, acc[i][7]);
            }
        }
    }

#pragma unroll
    for (int i = 0; i < 4; i++) {
        int row = base + r0 + i;
        if (row < n) {
            float* o = out + (long long)row * M + c0;
            *(float4*)(o)     = make_float4(acc[i][0], acc[i][1], acc[i][2], acc[i][3]);
            *(float4*)(o + 4) = make_float4(acc[i][4], acc[i][5], acc[i][6], acc[i][7]);
        }
    }
}

// Small GEMM for M=2 (layer 3), BN+ReLU fused on load.
template <int K>
__global__ void gemm2_bn_kernel(const float* __restrict__ X,
                                const float* __restrict__ W,
                                float* __restrict__ out, int n,
                                const float* __restrict__ stats,
                                const float* __restrict__ g,
                                const float* __restrict__ beta) {
    __shared__ float Ws[K * 2];
    __shared__ float sscale[K];
    __shared__ float sshift[K];
    __shared__ float xs[128 * K];
    const int tid = threadIdx.x;

    if (tid < K) {
        float inv_n = 1.0f / (float)n;
        float m = stats[tid] * inv_n;
        float v = stats[128 + tid] * inv_n - m * m;
        float sc = g[tid] * rsqrtf(v + 1e-5f);
        sscale[tid] = sc;
        sshift[tid] = beta[tid] - m * sc;
    }
    for (int i = tid; i < K * 2; i += 256) Ws[i] = W[i];
    __syncthreads();

    const int base = blockIdx.x * 128;
    constexpr int K4 = K / 4;
    for (int i = tid; i < 128 * K4; i += 256) {
        int rr = i / K4, kk = i % K4;
        int row = base + rr;
        float4 v = make_float4(0.f, 0.f, 0.f, 0.f);
        if (row < n) {
            v = *(const float4*)(X + (long long)row * K + kk * 4);
            int f = kk * 4;
            v.x = fmaxf(fmaf(v.x, sscale[f + 0], sshift[f + 0]), 0.f);
            v.y = fmaxf(fmaf(v.y, sscale[f + 1], sshift[f + 1]), 0.f);
            v.z = fmaxf(fmaf(v.z, sscale[f + 2], sshift[f + 2]), 0.f);
            v.w = fmaxf(fmaf(v.w, sscale[f + 3], sshift[f + 3]), 0.f);
        }
        *(float4*)&xs[rr * K + kk * 4] = v;
    }
    __syncthreads();

    const int col = tid % 2;
    const int r   = tid / 2;
    int row = base + r;
    if (row < n) {
        float acc = 0.0f;
        const float* xrow = xs + r * K;
#pragma unroll
        for (int k = 0; k < K; k++) acc = fmaf(xrow[k], Ws[k * 2 + col], acc);
        out[(long long)row * 2 + col] = acc;
    }
}

// ---------------------------------------------------------------------------
// CSR pull-aggregation, F=128. Warp per node (grid-stride), lane owns 4
// features. Fuses self-loop + bias + BN stats accumulation.
__global__ void __launch_bounds__(256)
csr_agg128_kernel(const int* __restrict__ csr_src,
                  const int* __restrict__ offsets,
                  const float* __restrict__ h,
                  const float* __restrict__ dinv,
                  const float* __restrict__ b,
                  float* __restrict__ out, int n,
                  float* __restrict__ stats) {
    __shared__ float ssum[128];
    __shared__ float ssq[128];
    const int tid  = threadIdx.x;
    const int lane = tid & 31;
    const int wid  = tid >> 5;
    if (tid < 128) { ssum[tid] = 0.f; ssq[tid] = 0.f; }
    __syncthreads();

    const float4* h4 = (const float4*)h;
    float4* out4 = (float4*)out;
    float4 bv = ((const float4*)b)[lane];

    float4 lsum = make_float4(0.f, 0.f, 0.f, 0.f);
    float4 lsq  = make_float4(0.f, 0.f, 0.f, 0.f);

    for (int node = blockIdx.x * 8 + wid; node < n; node += gridDim.x * 8) {
        const int e0 = offsets[node];
        const int e1 = offsets[node + 1];
        const float dn = dinv[node];
        float4 acc = make_float4(0.f, 0.f, 0.f, 0.f);

        int j = e0;
        for (; j + 4 <= e1; j += 4) {
            int sa = csr_src[j],     sb = csr_src[j + 1];
            int sc = csr_src[j + 2], sd = csr_src[j + 3];
            float na = dinv[sa] * dn, nb = dinv[sb] * dn;
            float nc = dinv[sc] * dn, nd = dinv[sd] * dn;
            float4 va = h4[(long long)sa * 32 + lane];
            float4 vb = h4[(long long)sb * 32 + lane];
            float4 vc = h4[(long long)sc * 32 + lane];
            float4 vd = h4[(long long)sd * 32 + lane];
            acc.x += va.x * na + vb.x * nb + vc.x * nc + vd.x * nd;
            acc.y += va.y * na + vb.y * nb + vc.y * nc + vd.y * nd;
            acc.z += va.z * na + vb.z * nb + vc.z * nc + vd.z * nd;
            acc.w += va.w * na + vb.w * nb + vc.w * nc + vd.w * nd;
        }
        for (; j < e1; j++) {
            int s = csr_src[j];
            float nm = dinv[s] * dn;
            float4 v = h4[(long long)s * 32 + lane];
            acc.x += v.x * nm; acc.y += v.y * nm;
            acc.z += v.z * nm; acc.w += v.w * nm;
        }
        float4 hv = h4[(long long)node * 32 + lane];
        float d2 = dn * dn;
        acc.x = fmaf(hv.x, d2, acc.x) + bv.x;
        acc.y = fmaf(hv.y, d2, acc.y) + bv.y;
        acc.z = fmaf(hv.z, d2, acc.z) + bv.z;
        acc.w = fmaf(hv.w, d2, acc.w) + bv.w;
        out4[(long long)node * 32 + lane] = acc;

        lsum.x += acc.x; lsum.y += acc.y; lsum.z += acc.z; lsum.w += acc.w;
        lsq.x = fmaf(acc.x, acc.x, lsq.x); lsq.y = fmaf(acc.y, acc.y, lsq.y);
        lsq.z = fmaf(acc.z, acc.z, lsq.z); lsq.w = fmaf(acc.w, acc.w, lsq.w);
    }

    atomicAdd(&ssum[lane * 4 + 0], lsum.x);
    atomicAdd(&ssum[lane * 4 + 1], lsum.y);
    atomicAdd(&ssum[lane * 4 + 2], lsum.z);
    atomicAdd(&ssum[lane * 4 + 3], lsum.w);
    atomicAdd(&ssq[lane * 4 + 0], lsq.x);
    atomicAdd(&ssq[lane * 4 + 1], lsq.y);
    atomicAdd(&ssq[lane * 4 + 2], lsq.z);
    atomicAdd(&ssq[lane * 4 + 3], lsq.w);
    __syncthreads();
    if (tid < 128) {
        atomicAdd(&stats[tid], ssum[tid]);
        atomicAdd(&stats[128 + tid], ssq[tid]);
    }
}

// F=64 version: lane owns 2 features (float2).
__global__ void __launch_bounds__(256)
csr_agg64_kernel(const int* __restrict__ csr_src,
                 const int* __restrict__ offsets,
                 const float* __restrict__ h,
                 const float* __restrict__ dinv,
                 const float* __restrict__ b,
                 float* __restrict__ out, int n,
                 float* __restrict__ stats) {
    __shared__ float ssum[64];
    __shared__ float ssq[64];
    const int tid  = threadIdx.x;
    const int lane = tid & 31;
    const int wid  = tid >> 5;
    if (tid < 64) { ssum[tid] = 0.f; ssq[tid] = 0.f; }
    __syncthreads();

    const float2* h2 = (const float2*)h;
    float2* out2 = (float2*)out;
    float2 bv = ((const float2*)b)[lane];

    float2 lsum = make_float2(0.f, 0.f);
    float2 lsq  = make_float2(0.f, 0.f);

    for (int node = blockIdx.x * 8 + wid; node < n; node += gridDim.x * 8) {
        const int e0 = offsets[node];
        const int e1 = offsets[node + 1];
        const float dn = dinv[node];
        float2 acc = make_float2(0.f, 0.f);

        int j = e0;
        for (; j + 4 <= e1; j += 4) {
            int sa = csr_src[j],     sb = csr_src[j + 1];
            int sc = csr_src[j + 2], sd = csr_src[j + 3];
            float na = dinv[sa] * dn, nb = dinv[sb] * dn;
            float nc = dinv[sc] * dn, nd = dinv[sd] * dn;
            float2 va = h2[(long long)sa * 32 + lane];
            float2 vb = h2[(long long)sb * 32 + lane];
            float2 vc = h2[(long long)sc * 32 + lane];
            float2 vd = h2[(long long)sd * 32 + lane];
            acc.x += va.x * na + vb.x * nb + vc.x * nc + vd.x * nd;
            acc.y += va.y * na + vb.y * nb + vc.y * nc + vd.y * nd;
        }
        for (; j < e1; j++) {
            int s = csr_src[j];
            float nm = dinv[s] * dn;
            float2 v = h2[(long long)s * 32 + lane];
            acc.x += v.x * nm; acc.y += v.y * nm;
        }
        float2 hv = h2[(long long)node * 32 + lane];
        float d2 = dn * dn;
        acc.x = fmaf(hv.x, d2, acc.x) + bv.x;
        acc.y = fmaf(hv.y, d2, acc.y) + bv.y;
        out2[(long long)node * 32 + lane] = acc;

        lsum.x += acc.x; lsum.y += acc.y;
        lsq.x = fmaf(acc.x, acc.x, lsq.x);
        lsq.y = fmaf(acc.y, acc.y, lsq.y);
    }

    atomicAdd(&ssum[lane * 2 + 0], lsum.x);
    atomicAdd(&ssum[lane * 2 + 1], lsum.y);
    atomicAdd(&ssq[lane * 2 + 0], lsq.x);
    atomicAdd(&ssq[lane * 2 + 1], lsq.y);
    __syncthreads();
    if (tid < 64) {
        atomicAdd(&stats[tid], ssum[tid]);
        atomicAdd(&stats[128 + tid], ssq[tid]);
    }
}

// F=2: thread per node; fuses self-loop + bias + log_softmax, writes d_out.
__global__ void __launch_bounds__(256)
csr_agg2_lsm_kernel(const int* __restrict__ csr_src,
                    const int* __restrict__ offsets,
                    const float* __restrict__ h,
                    const float* __restrict__ dinv,
                    const float* __restrict__ b,
                    float* __restrict__ out, int n) {
    int node = blockIdx.x * blockDim.x + threadIdx.x;
    if (node >= n) return;
    const float2* h2 = (const float2*)h;
    const int e0 = offsets[node];
    const int e1 = offsets[node + 1];
    const float dn = dinv[node];
    float ax = 0.f, ay = 0.f;
    int j = e0;
    for (; j + 4 <= e1; j += 4) {
        int sa = csr_src[j],     sb = csr_src[j + 1];
        int sc = csr_src[j + 2], sd = csr_src[j + 3];
        float na = dinv[sa] * dn, nb = dinv[sb] * dn;
        float nc = dinv[sc] * dn, nd = dinv[sd] * dn;
        float2 va = h2[sa], vb = h2[sb], vc = h2[sc], vd = h2[sd];
        ax += va.x * na + vb.x * nb + vc.x * nc + vd.x * nd;
        ay += va.y * na + vb.y * nb + vc.y * nc + vd.y * nd;
    }
    for (; j < e1; j++) {
        int s = csr_src[j];
        float nm = dinv[s] * dn;
        float2 v = h2[s];
        ax += v.x * nm; ay += v.y * nm;
    }
    float2 hv = h2[node];
    float d2 = dn * dn;
    float a = fmaf(hv.x, d2, ax) + b[0];
    float c = fmaf(hv.y, d2, ay) + b[1];
    float m = fmaxf(a, c);
    float l = m + logf(expf(a - m) + expf(c - m));
    out[2 * node]     = a - l;
    out[2 * node + 1] = c - l;
}

// ---------------------------------------------------------------------------
static inline int blocks_for(long long total, int tpb) {
    return (int)((total + tpb - 1) / tpb);
}

template <int K, int M, bool BN>
static void launch_gemm_rb(const float* X, const float* W, float* out, int n,
                           const float* stats, const float* g, const float* beta) {
    constexpr int TC = M / 8;
    constexpr int TR = 256 / TC;
    constexpr int ROWS = TR * 4;
    size_t sh = (size_t)(ROWS * K + 2 * K) * sizeof(float);
    cudaFuncSetAttribute(gemm_rb_kernel<K, M, BN>,
                         cudaFuncAttributeMaxDynamicSharedMemorySize, (int)sh);
    int grid = (n + ROWS - 1) / ROWS;
    gemm_rb_kernel<K, M, BN><<<grid, 256, sh>>>(X, W, out, n, stats, g, beta);
}

extern "C" void kernel_launch(void* const* d_in, const int* in_sizes, int n_in,
                              void* d_out, int out_size) {
    const float* x   = (const float*)d_in[0];
    const int*   ei  = (const int*)d_in[1];
    const float* W1 = (const float*)d_in[2];
    const float* b1 = (const float*)d_in[3];
    const float* g1 = (const float*)d_in[4];
    const float* be1= (const float*)d_in[5];
    const float* W2 = (const float*)d_in[6];
    const float* b2 = (const float*)d_in[7];
    const float* g2 = (const float*)d_in[8];
    const float* be2= (const float*)d_in[9];
    const float* W3 = (const float*)d_in[10];
    const float* b3 = (const float*)d_in[11];
    float* out = (float*)d_out;

    int       n = in_sizes[0] / 128;
    long long E = in_sizes[1] / 2;

    float *bufA, *bufB, *dinv, *stats;
    int *counts, *offsets, *cursor, *csr_src;
    cudaGetSymbolAddress((void**)&bufA,    g_bufA);
    cudaGetSymbolAddress((void**)&bufB,    g_bufB);
    cudaGetSymbolAddress((void**)&dinv,    g_dinv);
    cudaGetSymbolAddress((void**)&stats,   g_stats);
    cudaGetSymbolAddress((void**)&counts,  g_counts);
    cudaGetSymbolAddress((void**)&offsets, g_offsets);
    cudaGetSymbolAddress((void**)&cursor,  g_cursor);
    cudaGetSymbolAddress((void**)&csr_src, g_csr_src);

    // Side stream for the CSR build (overlaps with the layer-1 GEMM).
    static cudaStream_t s_side = nullptr;
    static cudaEvent_t ev_fork = nullptr, ev_join = nullptr;
    if (s_side == nullptr) {
        cudaStreamCreateWithFlags(&s_side, cudaStreamNonBlocking);
        cudaEventCreateWithFlags(&ev_fork, cudaEventDisableTiming);
        cudaEventCreateWithFlags(&ev_join, cudaEventDisableTiming);
    }

    const int AGG_GRID = 1184;   // 8 warps/block, grid-stride over nodes

    // ---- fork: CSR build + dinv + stats-zero on side stream -----------------
    cudaEventRecord(ev_fork, 0);
    cudaStreamWaitEvent(s_side, ev_fork, 0);
    cudaMemsetAsync(counts, 0, (size_t)n * sizeof(int), s_side);
    hist_kernel<<<blocks_for(E, 256), 256, 0, s_side>>>(ei, E, counts);
    scan_kernel<<<1, 1024, 0, s_side>>>(counts, offsets, dinv, n);
    cudaMemcpyAsync(cursor, offsets, (size_t)n * sizeof(int),
                    cudaMemcpyDeviceToDevice, s_side);
    scatter_kernel<<<blocks_for(E, 256), 256, 0, s_side>>>(ei, E, cursor, csr_src);
    cudaMemsetAsync(stats, 0, 256 * sizeof(float), s_side);
    cudaEventRecord(ev_join, s_side);

    // ---- layer 1 GEMM on main stream (concurrent with CSR build) ------------
    launch_gemm_rb<128, 128, false>(x, W1, bufA, n, nullptr, nullptr, nullptr);

    // ---- join, then aggregation + the rest of the chain ---------------------
    cudaStreamWaitEvent(0, ev_join, 0);
    csr_agg128_kernel<<<AGG_GRID, 256>>>(csr_src, offsets, bufA, dinv, b1,
                                         bufB, n, stats);

    // ---- layer 2: BN1+ReLU fused GEMM(128->64) + stats ----------------------
    launch_gemm_rb<128, 64, true>(bufB, W2, bufA, n, stats, g1, be1);
    cudaMemsetAsync(stats, 0, 256 * sizeof(float));
    csr_agg64_kernel<<<AGG_GRID, 256>>>(csr_src, offsets, bufA, dinv, b2,
                                        bufB, n, stats);

    // ---- layer 3: BN2+ReLU fused GEMM(64->2) + agg + log_softmax ------------
    gemm2_bn_kernel<64><<<blocks_for(n, 128), 256>>>(bufB, W3, bufA, n,
                                                     stats, g2, be2);
    csr_agg2_lsm_kernel<<<blocks_for(n, 256), 256>>>(csr_src, offsets, bufA,
                                                     dinv, b3, out, n);
}